// round 6
// baseline (speedup 1.0000x reference)
#include <cuda_runtime.h>

#define BB 16
#define SS 2048
#define KK 16
#define LL 64
#define II 256
#define NS (BB*SS)        // 32768
#define CH 16
#define NC (SS/CH)        // 128 chunks per batch
#define TOTCH (BB*NC)     // 2048 chunks total

#define SPB 16            // samples per emissions block
#define TPB 256

#define FULL 0xffffffffu

// Scratch (device globals; no allocation allowed)
__device__ float g_E[NS*KK];           // exp(clamp(em - rowmax, -80))
__device__ float g_emp[NS*KK];         // em - rowmax
__device__ float g_rowmax[NS];
__device__ float g_invvar[KK*LL];
__device__ float g_lvsum[KK];
__device__ float g_ws2[KK];
__device__ float g_A[KK*KK];           // row-softmaxed transition matrix
__device__ float g_Rn[TOTCH][KK*KK];   // per-chunk matrix, rows normalized (row max = 1)
__device__ float g_rowlog[TOTCH][KK];  // per-row log scale
__device__ float g_rmsum[TOTCH];       // sum of rowmax over chunk steps
__device__ float g_qb[TOTCH][KK];      // boundary q at chunk start (chunks >= 1)
__device__ float g_Cb[TOTCH];

// ---------------------------------------------------------------------------
// Setup: one warp-block per state k.
// ---------------------------------------------------------------------------
__global__ void __launch_bounds__(32) setup_kernel(
    const float* __restrict__ prior_logvar,
    const float* __restrict__ Ws,
    const float* __restrict__ trans)
{
    int w = blockIdx.x;
    int lane = threadIdx.x;

    float s = 0.f;
    #pragma unroll
    for (int e = 0; e < 2; e++) {
        int idx = w*LL + lane + 32*e;
        float lv = __ldg(prior_logvar + idx);
        g_invvar[idx] = 1.0f / (expf(lv) + 1e-8f);
        s += lv;
    }
    #pragma unroll
    for (int off = 16; off; off >>= 1) s += __shfl_xor_sync(FULL, s, off);
    if (lane == 0) g_lvsum[w] = s;

    float s2 = 0.f;
    #pragma unroll
    for (int e = 0; e < 8; e++) {
        float v = __ldg(Ws + w*II + lane + 32*e);
        s2 = fmaf(v, v, s2);
    }
    #pragma unroll
    for (int off = 16; off; off >>= 1) s2 += __shfl_xor_sync(FULL, s2, off);
    if (lane == 0) g_ws2[w] = s2;

    float v = (lane < 16) ? __ldg(trans + w*KK + (lane & 15)) : -1e30f;
    float mx = v;
    #pragma unroll
    for (int off = 8; off; off >>= 1) mx = fmaxf(mx, __shfl_xor_sync(FULL, mx, off));
    float ex = (lane < 16) ? expf(v - mx) : 0.f;
    float se = ex;
    #pragma unroll
    for (int off = 8; off; off >>= 1) se += __shfl_xor_sync(FULL, se, off);
    if (lane < 16) g_A[w*KK + lane] = expf(v - mx - logf(se));
}

// ---------------------------------------------------------------------------
// Emissions
// ---------------------------------------------------------------------------
__global__ void __launch_bounds__(TPB) emissions_kernel(
    const float* __restrict__ Y, const float* __restrict__ Z,
    const float* __restrict__ Wz, const float* __restrict__ Ws,
    const float* __restrict__ bdec, const float* __restrict__ mu)
{
    __shared__ __align__(16) float z_a[LL][SPB];      // [l][s]
    __shared__ __align__(16) float z_b[SPB][LL+4];    // [s][l] padded
    __shared__ __align__(16) float d_sh[SPB][II];
    __shared__ __align__(16) float ws_sh[KK][II+4];

    int tid = threadIdx.x;
    int s0 = blockIdx.x * SPB;

    #pragma unroll
    for (int e = 0; e < (SPB*LL)/TPB; e++) {
        int idx = tid + TPB*e;
        int s = idx >> 6, l = idx & 63;
        float v = Z[(s0 + s)*LL + l];
        z_a[l][s] = v;
        z_b[s][l] = v;
    }
    #pragma unroll
    for (int e = 0; e < (KK*II)/TPB; e++) {
        int idx = tid + TPB*e;
        ws_sh[idx >> 8][idx & 255] = Ws[idx];
    }
    __syncthreads();

    // ---- Phase A: base = b_dec + z @ Wz; d = y - base ----
    {
        float base[SPB];
        float bd = __ldg(bdec + tid);
        #pragma unroll
        for (int s = 0; s < SPB; s++) base[s] = bd;

        #pragma unroll 4
        for (int l = 0; l < LL; l++) {
            float wz = __ldg(Wz + l*II + tid);
            const float4* zr = (const float4*)&z_a[l][0];
            float4 za = zr[0], zb = zr[1], zc = zr[2], zd = zr[3];
            base[0]  = fmaf(za.x, wz, base[0]);
            base[1]  = fmaf(za.y, wz, base[1]);
            base[2]  = fmaf(za.z, wz, base[2]);
            base[3]  = fmaf(za.w, wz, base[3]);
            base[4]  = fmaf(zb.x, wz, base[4]);
            base[5]  = fmaf(zb.y, wz, base[5]);
            base[6]  = fmaf(zb.z, wz, base[6]);
            base[7]  = fmaf(zb.w, wz, base[7]);
            base[8]  = fmaf(zc.x, wz, base[8]);
            base[9]  = fmaf(zc.y, wz, base[9]);
            base[10] = fmaf(zc.z, wz, base[10]);
            base[11] = fmaf(zc.w, wz, base[11]);
            base[12] = fmaf(zd.x, wz, base[12]);
            base[13] = fmaf(zd.y, wz, base[13]);
            base[14] = fmaf(zd.z, wz, base[14]);
            base[15] = fmaf(zd.w, wz, base[15]);
        }
        #pragma unroll
        for (int s = 0; s < SPB; s++) {
            float y = __ldg(Y + (s0 + s)*II + tid);
            d_sh[s][tid] = y - base[s];
        }
    }
    __syncthreads();

    // ---- Phase B: thread (sample, state) ----
    int si = tid >> 4;
    int k  = tid & 15;

    float sd = 0.f;
    #pragma unroll
    for (int t = 0; t < 16; t++) {
        float dv = d_sh[si][t*16 + k];
        sd = fmaf(dv, dv, sd);
    }
    #pragma unroll
    for (int off = 8; off; off >>= 1) sd += __shfl_xor_sync(FULL, sd, off);

    float a0 = 0.f, a1 = 0.f, a2 = 0.f, a3 = 0.f;
    const float4* dr = (const float4*)&d_sh[si][0];
    const float4* wr = (const float4*)&ws_sh[k][0];
    #pragma unroll 8
    for (int i4 = 0; i4 < II/4; i4++) {
        float4 dv = dr[i4], wv = wr[i4];
        a0 = fmaf(dv.x, wv.x, a0);
        a1 = fmaf(dv.y, wv.y, a1);
        a2 = fmaf(dv.z, wv.z, a2);
        a3 = fmaf(dv.w, wv.w, a3);
    }
    float dot = (a0 + a1) + (a2 + a3);
    float accy = sd - 2.f*dot + __ldg(&g_ws2[k]);

    float b0 = 0.f, b1 = 0.f, b2 = 0.f, b3 = 0.f;
    const float4* zr = (const float4*)&z_b[si][0];
    const float4* mr = (const float4*)(mu + k*LL);
    const float4* ir = (const float4*)(g_invvar + k*LL);
    #pragma unroll
    for (int l4 = 0; l4 < LL/4; l4++) {
        float4 zv = zr[l4];
        float4 mv = __ldg(mr + l4);
        float4 iv = __ldg(ir + l4);
        float t0 = zv.x - mv.x; b0 = fmaf(t0*t0, iv.x, b0);
        float t1 = zv.y - mv.y; b1 = fmaf(t1*t1, iv.y, b1);
        float t2 = zv.z - mv.z; b2 = fmaf(t2*t2, iv.z, b2);
        float t3 = zv.w - mv.w; b3 = fmaf(t3*t3, iv.w, b3);
    }
    float accz = (b0 + b1) + (b2 + b3);

    const float LLOG2PI = 117.62413f;  // 64 * log(2*pi)
    float em = -0.5f*accy - 0.5f*(__ldg(&g_lvsum[k]) + accz + LLOG2PI);

    float m = em;
    #pragma unroll
    for (int off = 8; off; off >>= 1)
        m = fmaxf(m, __shfl_xor_sync(FULL, m, off));

    float emp = em - m;
    float E = __expf(fmaxf(emp, -80.f));

    int sample = s0 + si;
    g_E[sample*KK + k]   = E;
    g_emp[sample*KK + k] = emp;
    if (k == 0) g_rowmax[sample] = m;
}

// ---------------------------------------------------------------------------
// Phase 1: per-chunk (16 steps) matrix product R_c = prod M_t, M_t = A diag(E_t).
// One warp per chunk. Lane (i = lane>>1, half h = lane&1) owns R[i][h*8+kk].
// ---------------------------------------------------------------------------
__global__ void __launch_bounds__(32) phase1_kernel() {
    int c = blockIdx.x;
    int lane = threadIdx.x;
    int b = c / NC, cl = c % NC;
    int i = lane >> 1, h = lane & 1;

    float a[KK][8];
    #pragma unroll
    for (int j = 0; j < KK; j++)
        #pragma unroll
        for (int kk = 0; kk < 8; kk++)
            a[j][kk] = g_A[j*KK + h*8 + kk];

    float R[8];
    #pragma unroll
    for (int kk = 0; kk < 8; kk++)
        R[kk] = (i == h*8 + kk) ? 1.f : 0.f;

    float rowlog = 0.f, rmsum = 0.f;

    int t0 = b*SS + cl*CH;
    int us = (cl == 0) ? 1 : 0;
    const float* prm = g_rowmax + t0;

    float E[8], En[8];
    {
        const float4* p4 = (const float4*)(g_E + (size_t)(t0 + us)*KK + h*8);
        float4 q0 = __ldg(p4+0), q1 = __ldg(p4+1);
        E[0]=q0.x; E[1]=q0.y; E[2]=q0.z; E[3]=q0.w;
        E[4]=q1.x; E[5]=q1.y; E[6]=q1.z; E[7]=q1.w;
    }
    float rmc = __ldg(prm + us), rmn = 0.f;

    #pragma unroll
    for (int u = 0; u < CH; u++) {
        if (u < us) continue;
        if (u + 1 < CH) {
            const float4* p4 = (const float4*)(g_E + (size_t)(t0 + u + 1)*KK + h*8);
            float4 q0 = __ldg(p4+0), q1 = __ldg(p4+1);
            En[0]=q0.x; En[1]=q0.y; En[2]=q0.z; En[3]=q0.w;
            En[4]=q1.x; En[5]=q1.y; En[6]=q1.z; En[7]=q1.w;
            rmn = __ldg(prm + u + 1);
        }
        rmsum += rmc;

        float rp[8];
        #pragma unroll
        for (int j = 0; j < 8; j++) rp[j] = __shfl_xor_sync(FULL, R[j], 1);
        float rlo[8], rhi[8];
        #pragma unroll
        for (int j = 0; j < 8; j++) {
            rlo[j] = h ? rp[j] : R[j];
            rhi[j] = h ? R[j] : rp[j];
        }
        float nw[8];
        #pragma unroll
        for (int kk = 0; kk < 8; kk++) {
            float s0 = 0.f, s1 = 0.f;
            #pragma unroll
            for (int j = 0; j < 8; j++) {
                s0 = fmaf(rlo[j], a[j][kk],   s0);
                s1 = fmaf(rhi[j], a[j+8][kk], s1);
            }
            nw[kk] = (s0 + s1) * E[kk];
        }
        #pragma unroll
        for (int kk = 0; kk < 8; kk++) R[kk] = nw[kk];

        if (((u + 1) & 7) == 0) {
            float mx = R[0];
            #pragma unroll
            for (int kk = 1; kk < 8; kk++) mx = fmaxf(mx, R[kk]);
            mx = fmaxf(mx, __shfl_xor_sync(FULL, mx, 1));
            mx = fmaxf(mx, 1e-37f);
            float inv = __fdividef(1.f, mx);
            #pragma unroll
            for (int kk = 0; kk < 8; kk++) R[kk] *= inv;
            rowlog += __logf(mx);
        }

        #pragma unroll
        for (int kk = 0; kk < 8; kk++) E[kk] = En[kk];
        rmc = rmn;
    }

    #pragma unroll
    for (int kk = 0; kk < 8; kk++)
        g_Rn[c][i*KK + h*8 + kk] = R[kk];
    if (h == 0) g_rowlog[c][i] = rowlog;
    if (lane == 0) g_rmsum[c] = rmsum;
}

// ---------------------------------------------------------------------------
// Phase 2: one 256-thread block per batch, 128KB+ dynamic smem.
// Staging warps build all 128 scaled chunk matrices (float4 coalesced);
// warp 0 then runs 128 sequential combines with a shfl-dot-only chain.
// Row-normalized chunk matrices guarantee q_max <= v_max <= 16*q_max, so
// renorm every 16 combines is safe (growth <= 16^16 ~ 1.8e19 < fp32 max).
// ---------------------------------------------------------------------------
__global__ void __launch_bounds__(256) phase2_kernel(const float* __restrict__ start_logits) {
    extern __shared__ __align__(16) float sm2[];
    float* Bs = sm2;               // [NC][16][16]
    float* rc = sm2 + NC*256;      // [NC]

    int b = blockIdx.x;
    int tid = threadIdx.x;
    int w = tid >> 5, lane = tid & 31;
    int kk = lane & 15;

    // ---- staging: warp w handles chunks w, w+8, ..., w+120 ----
    #pragma unroll
    for (int cc = 0; cc < NC/8; cc++) {
        int c = w + cc*8;
        int gc = b*NC + c;
        float rl = (lane < 16) ? __ldg(&g_rowlog[gc][lane]) : -3.4e38f;
        float rlmax = rl;
        #pragma unroll
        for (int off = 8; off; off >>= 1)
            rlmax = fmaxf(rlmax, __shfl_xor_sync(FULL, rlmax, off));
        float smy = __expf(rl - rlmax);   // valid on lanes < 16

        const float4* pr = (const float4*)(&g_Rn[gc][0]);
        float4 r0 = __ldg(pr + lane*2);
        float4 r1 = __ldg(pr + lane*2 + 1);
        float s = __shfl_sync(FULL, smy, lane >> 1);
        r0.x *= s; r0.y *= s; r0.z *= s; r0.w *= s;
        r1.x *= s; r1.y *= s; r1.z *= s; r1.w *= s;
        float4* ps = (float4*)(Bs + c*256 + lane*8);
        ps[0] = r0; ps[1] = r1;
        if (lane == 0) rc[c] = __ldg(&g_rmsum[gc]) + rlmax;
    }
    __syncthreads();

    if (w != 0) return;

    // ---- warp 0: init with step 0 ----
    float sv = __ldg(start_logits + kk);
    float sm = sv;
    #pragma unroll
    for (int off = 8; off; off >>= 1) sm = fmaxf(sm, __shfl_xor_sync(FULL, sm, off));
    float se = __expf(sv - sm);
    #pragma unroll
    for (int off = 8; off; off >>= 1) se += __shfl_xor_sync(FULL, se, off);
    float lstart = sv - sm - __logf(se);

    float e0 = __ldg(&g_emp[(size_t)(b*SS)*KK + kk]);
    float t = lstart + e0;
    float m0 = t;
    #pragma unroll
    for (int off = 8; off; off >>= 1) m0 = fmaxf(m0, __shfl_xor_sync(FULL, m0, off));
    float q = __expf(t - m0);
    float C = __ldg(&g_rowmax[b*SS]) + m0;

    float Bc[16], Bn[16];
    #pragma unroll
    for (int i = 0; i < 16; i++) Bc[i] = Bs[i*16 + kk];

    for (int c = 0; c < NC; c++) {
        int gc = b*NC + c;
        if (c > 0) {
            if (lane < 16) g_qb[gc][kk] = q;
            if (lane == 0) g_Cb[gc] = C;
        }
        if (c + 1 < NC) {
            #pragma unroll
            for (int i = 0; i < 16; i++) Bn[i] = Bs[(c+1)*256 + i*16 + kk];
        }

        float s0 = 0.f, s1 = 0.f, s2 = 0.f, s3 = 0.f;
        #pragma unroll
        for (int j = 0; j < 16; j += 4) {
            s0 = fmaf(__shfl_sync(FULL, q, j + 0), Bc[j + 0], s0);
            s1 = fmaf(__shfl_sync(FULL, q, j + 1), Bc[j + 1], s1);
            s2 = fmaf(__shfl_sync(FULL, q, j + 2), Bc[j + 2], s2);
            s3 = fmaf(__shfl_sync(FULL, q, j + 3), Bc[j + 3], s3);
        }
        float v = (s0 + s1) + (s2 + s3);
        C += rc[c];

        if ((c & 15) == 15) {
            float mv = v;
            #pragma unroll
            for (int off = 8; off; off >>= 1)
                mv = fmaxf(mv, __shfl_xor_sync(FULL, mv, off));
            mv = fmaxf(mv, 1e-37f);
            q = __fdividef(v, mv);
            C += __logf(mv);
        } else {
            q = v;
        }

        #pragma unroll
        for (int i = 0; i < 16; i++) Bc[i] = Bn[i];
    }
}

// ---------------------------------------------------------------------------
// Phase 3: per-chunk (16 steps) vector recursion from stored boundary.
// One warp per chunk, everything preloaded, no renorm on the chain.
// ---------------------------------------------------------------------------
__global__ void __launch_bounds__(32) phase3_kernel(
    const float* __restrict__ start_logits, float* __restrict__ out)
{
    int c = blockIdx.x;
    int lane = threadIdx.x;
    int b = c / NC, cl = c % NC;
    int kk = lane & 15;

    float acol[KK];
    #pragma unroll
    for (int j = 0; j < KK; j++) acol[j] = __ldg(&g_A[j*KK + kk]);

    const float* pE = g_E   + (size_t)(b*SS + cl*CH)*KK;
    const float* pP = g_emp + (size_t)(b*SS + cl*CH)*KK;
    const float* prm = g_rowmax + b*SS + cl*CH;
    float* ob = out + (size_t)(b*SS + cl*CH)*KK;

    float bufE[CH], bufP[CH], rm[CH];
    #pragma unroll
    for (int u = 0; u < CH; u++) {
        bufE[u] = __ldg(pE + u*KK + kk);
        bufP[u] = __ldg(pP + u*KK + kk);
        rm[u]   = __ldg(prm + u);
    }

    float q, C;
    if (cl == 0) {
        float sv = __ldg(start_logits + kk);
        float sm = sv;
        #pragma unroll
        for (int off = 8; off; off >>= 1) sm = fmaxf(sm, __shfl_xor_sync(FULL, sm, off));
        float se = __expf(sv - sm);
        #pragma unroll
        for (int off = 8; off; off >>= 1) se += __shfl_xor_sync(FULL, se, off);
        float lstart = sv - sm - __logf(se);

        float a0 = lstart + bufP[0] + rm[0];
        if (lane < 16) ob[kk] = a0;
        q = __expf(fmaxf(lstart + bufP[0], -80.f));
        C = rm[0];
    } else {
        q = __ldg(&g_qb[c][kk]);
        C = __ldg(&g_Cb[c]);
    }

    #pragma unroll
    for (int u = 0; u < CH; u++) {
        if (cl == 0 && u == 0) continue;
        float s0 = 0.f, s1 = 0.f, s2 = 0.f, s3 = 0.f;
        #pragma unroll
        for (int j = 0; j < KK; j += 4) {
            s0 = fmaf(__shfl_sync(FULL, q, j + 0), acol[j + 0], s0);
            s1 = fmaf(__shfl_sync(FULL, q, j + 1), acol[j + 1], s1);
            s2 = fmaf(__shfl_sync(FULL, q, j + 2), acol[j + 2], s2);
            s3 = fmaf(__shfl_sync(FULL, q, j + 3), acol[j + 3], s3);
        }
        float ssum = (s0 + s1) + (s2 + s3);
        ssum = fmaxf(ssum, 1e-37f);
        float ov = C + rm[u] + bufP[u] + __logf(ssum);
        if (lane < 16) ob[u*KK + kk] = ov;
        q = ssum * bufE[u];
        C += rm[u];
    }
}

// ---------------------------------------------------------------------------
extern "C" void kernel_launch(void* const* d_in, const int* in_sizes, int n_in,
                              void* d_out, int out_size) {
    const float* y   = (const float*)d_in[0];
    const float* z   = (const float*)d_in[1];
    const float* st  = (const float*)d_in[2];
    const float* tr  = (const float*)d_in[3];
    const float* mu  = (const float*)d_in[4];
    const float* lv  = (const float*)d_in[5];
    const float* wz  = (const float*)d_in[6];
    const float* ws  = (const float*)d_in[7];
    const float* bd  = (const float*)d_in[8];
    float* out = (float*)d_out;

    int p2_smem = (NC*256 + NC) * sizeof(float);   // ~131.5 KB
    cudaFuncSetAttribute(phase2_kernel,
                         cudaFuncAttributeMaxDynamicSharedMemorySize, p2_smem);

    setup_kernel<<<KK, 32>>>(lv, ws, tr);
    emissions_kernel<<<NS/SPB, TPB>>>(y, z, wz, ws, bd, mu);
    phase1_kernel<<<TOTCH, 32>>>();
    phase2_kernel<<<BB, 256, p2_smem>>>(st);
    phase3_kernel<<<TOTCH, 32>>>(st, out);
}

// round 7
// speedup vs baseline: 1.0471x; 1.0471x over previous
#include <cuda_runtime.h>

#define BB 16
#define SS 2048
#define KK 16
#define LL 64
#define II 256
#define NS (BB*SS)        // 32768
#define CH 16
#define NC (SS/CH)        // 128 chunks per batch
#define TOTCH (BB*NC)     // 2048 chunks total
#define SUPW 8            // chunks per super-chunk
#define NSUP (NC/SUPW)    // 16 super-chunks per batch
#define TOTSUP (BB*NSUP)  // 256

#define SPB 16            // samples per emissions block
#define TPB 256

#define FULL 0xffffffffu

// Scratch (device globals; no allocation allowed)
__device__ float g_E[NS*KK];            // exp(clamp(em - rowmax, -80))
__device__ float g_emp[NS*KK];          // em - rowmax
__device__ float g_rowmax[NS];
__device__ float g_invvar[KK*LL];
__device__ float g_lvsum[KK];
__device__ float g_ws2[KK];
__device__ float g_A[KK*KK];            // row-softmaxed transition matrix
__device__ float g_Rn[TOTCH][KK*KK];    // per-chunk matrix, rows normalized (row max = 1)
__device__ float g_rowlog[TOTCH][KK];   // per-row log scale
__device__ float g_rmsum[TOTCH];        // sum of rowmax over chunk steps
__device__ float g_Sn[TOTSUP][KK*KK];   // super-chunk matrices, rows normalized
__device__ float g_srowlog[TOTSUP][KK];
__device__ float g_srmsum[TOTSUP];
__device__ float g_qb[TOTCH][KK];       // boundary q at chunk start (cl >= 1)
__device__ float g_Cb[TOTCH];

// ---------------------------------------------------------------------------
// Setup: one warp-block per state k.
// ---------------------------------------------------------------------------
__global__ void __launch_bounds__(32) setup_kernel(
    const float* __restrict__ prior_logvar,
    const float* __restrict__ Ws,
    const float* __restrict__ trans)
{
    int w = blockIdx.x;
    int lane = threadIdx.x;

    float s = 0.f;
    #pragma unroll
    for (int e = 0; e < 2; e++) {
        int idx = w*LL + lane + 32*e;
        float lv = __ldg(prior_logvar + idx);
        g_invvar[idx] = 1.0f / (expf(lv) + 1e-8f);
        s += lv;
    }
    #pragma unroll
    for (int off = 16; off; off >>= 1) s += __shfl_xor_sync(FULL, s, off);
    if (lane == 0) g_lvsum[w] = s;

    float s2 = 0.f;
    #pragma unroll
    for (int e = 0; e < 8; e++) {
        float v = __ldg(Ws + w*II + lane + 32*e);
        s2 = fmaf(v, v, s2);
    }
    #pragma unroll
    for (int off = 16; off; off >>= 1) s2 += __shfl_xor_sync(FULL, s2, off);
    if (lane == 0) g_ws2[w] = s2;

    float v = (lane < 16) ? __ldg(trans + w*KK + (lane & 15)) : -1e30f;
    float mx = v;
    #pragma unroll
    for (int off = 8; off; off >>= 1) mx = fmaxf(mx, __shfl_xor_sync(FULL, mx, off));
    float ex = (lane < 16) ? expf(v - mx) : 0.f;
    float se = ex;
    #pragma unroll
    for (int off = 8; off; off >>= 1) se += __shfl_xor_sync(FULL, se, off);
    if (lane < 16) g_A[w*KK + lane] = expf(v - mx - logf(se));
}

// ---------------------------------------------------------------------------
// Emissions
// ---------------------------------------------------------------------------
__global__ void __launch_bounds__(TPB) emissions_kernel(
    const float* __restrict__ Y, const float* __restrict__ Z,
    const float* __restrict__ Wz, const float* __restrict__ Ws,
    const float* __restrict__ bdec, const float* __restrict__ mu)
{
    __shared__ __align__(16) float z_a[LL][SPB];      // [l][s]
    __shared__ __align__(16) float z_b[SPB][LL+4];    // [s][l] padded
    __shared__ __align__(16) float d_sh[SPB][II];
    __shared__ __align__(16) float ws_sh[KK][II+4];

    int tid = threadIdx.x;
    int s0 = blockIdx.x * SPB;

    #pragma unroll
    for (int e = 0; e < (SPB*LL)/TPB; e++) {
        int idx = tid + TPB*e;
        int s = idx >> 6, l = idx & 63;
        float v = Z[(s0 + s)*LL + l];
        z_a[l][s] = v;
        z_b[s][l] = v;
    }
    #pragma unroll
    for (int e = 0; e < (KK*II)/TPB; e++) {
        int idx = tid + TPB*e;
        ws_sh[idx >> 8][idx & 255] = Ws[idx];
    }
    __syncthreads();

    // ---- Phase A: base = b_dec + z @ Wz; d = y - base ----
    {
        float base[SPB];
        float bd = __ldg(bdec + tid);
        #pragma unroll
        for (int s = 0; s < SPB; s++) base[s] = bd;

        #pragma unroll 4
        for (int l = 0; l < LL; l++) {
            float wz = __ldg(Wz + l*II + tid);
            const float4* zr = (const float4*)&z_a[l][0];
            float4 za = zr[0], zb = zr[1], zc = zr[2], zd = zr[3];
            base[0]  = fmaf(za.x, wz, base[0]);
            base[1]  = fmaf(za.y, wz, base[1]);
            base[2]  = fmaf(za.z, wz, base[2]);
            base[3]  = fmaf(za.w, wz, base[3]);
            base[4]  = fmaf(zb.x, wz, base[4]);
            base[5]  = fmaf(zb.y, wz, base[5]);
            base[6]  = fmaf(zb.z, wz, base[6]);
            base[7]  = fmaf(zb.w, wz, base[7]);
            base[8]  = fmaf(zc.x, wz, base[8]);
            base[9]  = fmaf(zc.y, wz, base[9]);
            base[10] = fmaf(zc.z, wz, base[10]);
            base[11] = fmaf(zc.w, wz, base[11]);
            base[12] = fmaf(zd.x, wz, base[12]);
            base[13] = fmaf(zd.y, wz, base[13]);
            base[14] = fmaf(zd.z, wz, base[14]);
            base[15] = fmaf(zd.w, wz, base[15]);
        }
        #pragma unroll
        for (int s = 0; s < SPB; s++) {
            float y = __ldg(Y + (s0 + s)*II + tid);
            d_sh[s][tid] = y - base[s];
        }
    }
    __syncthreads();

    // ---- Phase B: thread (sample, state) ----
    int si = tid >> 4;
    int k  = tid & 15;

    float sd = 0.f;
    #pragma unroll
    for (int t = 0; t < 16; t++) {
        float dv = d_sh[si][t*16 + k];
        sd = fmaf(dv, dv, sd);
    }
    #pragma unroll
    for (int off = 8; off; off >>= 1) sd += __shfl_xor_sync(FULL, sd, off);

    float a0 = 0.f, a1 = 0.f, a2 = 0.f, a3 = 0.f;
    const float4* dr = (const float4*)&d_sh[si][0];
    const float4* wr = (const float4*)&ws_sh[k][0];
    #pragma unroll 8
    for (int i4 = 0; i4 < II/4; i4++) {
        float4 dv = dr[i4], wv = wr[i4];
        a0 = fmaf(dv.x, wv.x, a0);
        a1 = fmaf(dv.y, wv.y, a1);
        a2 = fmaf(dv.z, wv.z, a2);
        a3 = fmaf(dv.w, wv.w, a3);
    }
    float dot = (a0 + a1) + (a2 + a3);
    float accy = sd - 2.f*dot + __ldg(&g_ws2[k]);

    float b0 = 0.f, b1 = 0.f, b2 = 0.f, b3 = 0.f;
    const float4* zr = (const float4*)&z_b[si][0];
    const float4* mr = (const float4*)(mu + k*LL);
    const float4* ir = (const float4*)(g_invvar + k*LL);
    #pragma unroll
    for (int l4 = 0; l4 < LL/4; l4++) {
        float4 zv = zr[l4];
        float4 mv = __ldg(mr + l4);
        float4 iv = __ldg(ir + l4);
        float t0 = zv.x - mv.x; b0 = fmaf(t0*t0, iv.x, b0);
        float t1 = zv.y - mv.y; b1 = fmaf(t1*t1, iv.y, b1);
        float t2 = zv.z - mv.z; b2 = fmaf(t2*t2, iv.z, b2);
        float t3 = zv.w - mv.w; b3 = fmaf(t3*t3, iv.w, b3);
    }
    float accz = (b0 + b1) + (b2 + b3);

    const float LLOG2PI = 117.62413f;  // 64 * log(2*pi)
    float em = -0.5f*accy - 0.5f*(__ldg(&g_lvsum[k]) + accz + LLOG2PI);

    float m = em;
    #pragma unroll
    for (int off = 8; off; off >>= 1)
        m = fmaxf(m, __shfl_xor_sync(FULL, m, off));

    float emp = em - m;
    float E = __expf(fmaxf(emp, -80.f));

    int sample = s0 + si;
    g_E[sample*KK + k]   = E;
    g_emp[sample*KK + k] = emp;
    if (k == 0) g_rowmax[sample] = m;
}

// ---------------------------------------------------------------------------
// Phase 1: per-chunk (16 steps) matrix product R_c = prod M_t, M_t = A diag(E_t).
// One warp per chunk. Lane (i = lane>>1, half h = lane&1) owns R[i][h*8+kk].
// ---------------------------------------------------------------------------
__global__ void __launch_bounds__(32) phase1_kernel() {
    int c = blockIdx.x;
    int lane = threadIdx.x;
    int b = c / NC, cl = c % NC;
    int i = lane >> 1, h = lane & 1;

    float a[KK][8];
    #pragma unroll
    for (int j = 0; j < KK; j++)
        #pragma unroll
        for (int kk = 0; kk < 8; kk++)
            a[j][kk] = g_A[j*KK + h*8 + kk];

    float R[8];
    #pragma unroll
    for (int kk = 0; kk < 8; kk++)
        R[kk] = (i == h*8 + kk) ? 1.f : 0.f;

    float rowlog = 0.f, rmsum = 0.f;

    int t0 = b*SS + cl*CH;
    int us = (cl == 0) ? 1 : 0;
    const float* prm = g_rowmax + t0;

    float E[8], En[8];
    {
        const float4* p4 = (const float4*)(g_E + (size_t)(t0 + us)*KK + h*8);
        float4 q0 = __ldg(p4+0), q1 = __ldg(p4+1);
        E[0]=q0.x; E[1]=q0.y; E[2]=q0.z; E[3]=q0.w;
        E[4]=q1.x; E[5]=q1.y; E[6]=q1.z; E[7]=q1.w;
    }
    float rmc = __ldg(prm + us), rmn = 0.f;

    #pragma unroll
    for (int u = 0; u < CH; u++) {
        if (u < us) continue;
        if (u + 1 < CH) {
            const float4* p4 = (const float4*)(g_E + (size_t)(t0 + u + 1)*KK + h*8);
            float4 q0 = __ldg(p4+0), q1 = __ldg(p4+1);
            En[0]=q0.x; En[1]=q0.y; En[2]=q0.z; En[3]=q0.w;
            En[4]=q1.x; En[5]=q1.y; En[6]=q1.z; En[7]=q1.w;
            rmn = __ldg(prm + u + 1);
        }
        rmsum += rmc;

        float rp[8];
        #pragma unroll
        for (int j = 0; j < 8; j++) rp[j] = __shfl_xor_sync(FULL, R[j], 1);
        float rlo[8], rhi[8];
        #pragma unroll
        for (int j = 0; j < 8; j++) {
            rlo[j] = h ? rp[j] : R[j];
            rhi[j] = h ? R[j] : rp[j];
        }
        float nw[8];
        #pragma unroll
        for (int kk = 0; kk < 8; kk++) {
            float s0 = 0.f, s1 = 0.f;
            #pragma unroll
            for (int j = 0; j < 8; j++) {
                s0 = fmaf(rlo[j], a[j][kk],   s0);
                s1 = fmaf(rhi[j], a[j+8][kk], s1);
            }
            nw[kk] = (s0 + s1) * E[kk];
        }
        #pragma unroll
        for (int kk = 0; kk < 8; kk++) R[kk] = nw[kk];

        if (((u + 1) & 7) == 0) {
            float mx = R[0];
            #pragma unroll
            for (int kk = 1; kk < 8; kk++) mx = fmaxf(mx, R[kk]);
            mx = fmaxf(mx, __shfl_xor_sync(FULL, mx, 1));
            mx = fmaxf(mx, 1e-37f);
            float inv = __fdividef(1.f, mx);
            #pragma unroll
            for (int kk = 0; kk < 8; kk++) R[kk] *= inv;
            rowlog += __logf(mx);
        }

        #pragma unroll
        for (int kk = 0; kk < 8; kk++) E[kk] = En[kk];
        rmc = rmn;
    }

    #pragma unroll
    for (int kk = 0; kk < 8; kk++)
        g_Rn[c][i*KK + h*8 + kk] = R[kk];
    if (h == 0) g_rowlog[c][i] = rowlog;
    if (lane == 0) g_rmsum[c] = rmsum;
}

// ---------------------------------------------------------------------------
// Phase 1b: combine 8 chunk matrices into one super-chunk matrix.
// One warp per super-chunk (256 warps, fully parallel).
// ---------------------------------------------------------------------------
__global__ void __launch_bounds__(32) phase1b_kernel() {
    int sup = blockIdx.x;
    int lane = threadIdx.x;
    int b = sup / NSUP, sl = sup % NSUP;
    int c0 = b*NC + sl*SUPW;
    int i = lane >> 1, h = lane & 1;

    float acc[8];
    {
        const float4* pr = (const float4*)(&g_Rn[c0][i*KK + h*8]);
        float4 r0 = __ldg(pr), r1 = __ldg(pr+1);
        acc[0]=r0.x; acc[1]=r0.y; acc[2]=r0.z; acc[3]=r0.w;
        acc[4]=r1.x; acc[5]=r1.y; acc[6]=r1.z; acc[7]=r1.w;
    }
    float rlA = __ldg(&g_rowlog[c0][i]);

    for (int m = 1; m < SUPW; m++) {
        int cm = c0 + m;
        float rl = (lane < 16) ? __ldg(&g_rowlog[cm][lane]) : -3.4e38f;
        float rlmax = rl;
        #pragma unroll
        for (int off = 16; off; off >>= 1)
            rlmax = fmaxf(rlmax, __shfl_xor_sync(FULL, rlmax, off));
        float sB = __expf(rl - rlmax);   // lanes < 16 valid

        float bm[KK][8];
        #pragma unroll
        for (int j = 0; j < KK; j++) {
            const float4* pb = (const float4*)(&g_Rn[cm][j*KK + h*8]);
            float4 b0 = __ldg(pb), b1 = __ldg(pb+1);
            float s = __shfl_sync(FULL, sB, j);
            bm[j][0]=b0.x*s; bm[j][1]=b0.y*s; bm[j][2]=b0.z*s; bm[j][3]=b0.w*s;
            bm[j][4]=b1.x*s; bm[j][5]=b1.y*s; bm[j][6]=b1.z*s; bm[j][7]=b1.w*s;
        }

        float rp[8];
        #pragma unroll
        for (int j = 0; j < 8; j++) rp[j] = __shfl_xor_sync(FULL, acc[j], 1);
        float ar[16];
        #pragma unroll
        for (int j = 0; j < 8; j++) {
            ar[j]   = h ? rp[j]  : acc[j];
            ar[j+8] = h ? acc[j] : rp[j];
        }
        float nw[8];
        #pragma unroll
        for (int kk = 0; kk < 8; kk++) {
            float s0 = 0.f, s1 = 0.f;
            #pragma unroll
            for (int j = 0; j < 8; j++) {
                s0 = fmaf(ar[j],   bm[j][kk],   s0);
                s1 = fmaf(ar[j+8], bm[j+8][kk], s1);
            }
            nw[kk] = s0 + s1;
        }
        float mx = nw[0];
        #pragma unroll
        for (int kk = 1; kk < 8; kk++) mx = fmaxf(mx, nw[kk]);
        mx = fmaxf(mx, __shfl_xor_sync(FULL, mx, 1));
        mx = fmaxf(mx, 1e-37f);
        float inv = __fdividef(1.f, mx);
        #pragma unroll
        for (int kk = 0; kk < 8; kk++) acc[kk] = nw[kk] * inv;
        rlA += rlmax + __logf(mx);
    }

    #pragma unroll
    for (int kk = 0; kk < 8; kk++)
        g_Sn[sup][i*KK + h*8 + kk] = acc[kk];
    if (h == 0) g_srowlog[sup][i] = rlA;
    if (lane == 0) {
        float s = 0.f;
        #pragma unroll
        for (int m = 0; m < SUPW; m++) s += g_rmsum[c0 + m];
        g_srmsum[sup] = s;
    }
}

// ---------------------------------------------------------------------------
// Phase 2: one 256-thread block per batch.
// (a) 8 warps stage the 16 scaled super-matrices in SMEM;
// (b) warp 0 runs 16 serial combines, writes super boundaries to SMEM;
// (c) all 8 warps propagate boundaries down to chunk level (8 steps each).
// ---------------------------------------------------------------------------
__global__ void __launch_bounds__(256) phase2_kernel(const float* __restrict__ start_logits) {
    __shared__ __align__(16) float Bs[NSUP][KK][KK];   // 16 KB
    __shared__ float rc[NSUP];
    __shared__ float qs_sh[NSUP][KK];
    __shared__ float Cs_sh[NSUP];

    int b = blockIdx.x;
    int tid = threadIdx.x;
    int w = tid >> 5, lane = tid & 31;
    int kk = lane & 15;

    // ---- (a) staging ----
    #pragma unroll
    for (int ss = 0; ss < 2; ss++) {
        int s = w*2 + ss;
        int gs = b*NSUP + s;
        float rl = (lane < 16) ? __ldg(&g_srowlog[gs][lane]) : -3.4e38f;
        float rlmax = rl;
        #pragma unroll
        for (int off = 16; off; off >>= 1)
            rlmax = fmaxf(rlmax, __shfl_xor_sync(FULL, rlmax, off));
        float smy = __expf(rl - rlmax);

        const float4* pr = (const float4*)(&g_Sn[gs][0]);
        float4 r0 = __ldg(pr + lane*2);
        float4 r1 = __ldg(pr + lane*2 + 1);
        float sc = __shfl_sync(FULL, smy, lane >> 1);
        r0.x *= sc; r0.y *= sc; r0.z *= sc; r0.w *= sc;
        r1.x *= sc; r1.y *= sc; r1.z *= sc; r1.w *= sc;
        float4* ps = (float4*)(&Bs[s][0][0] + lane*8);
        ps[0] = r0; ps[1] = r1;
        if (lane == 0) rc[s] = __ldg(&g_srmsum[gs]) + rlmax;
    }
    __syncthreads();

    // ---- (b) warp 0: serial combines over 16 super-chunks ----
    if (w == 0) {
        float sv = __ldg(start_logits + kk);
        float sm = sv;
        #pragma unroll
        for (int off = 8; off; off >>= 1) sm = fmaxf(sm, __shfl_xor_sync(FULL, sm, off));
        float se = __expf(sv - sm);
        #pragma unroll
        for (int off = 8; off; off >>= 1) se += __shfl_xor_sync(FULL, se, off);
        float lstart = sv - sm - __logf(se);

        float e0 = __ldg(&g_emp[(size_t)(b*SS)*KK + kk]);
        float t = lstart + e0;
        float m0 = t;
        #pragma unroll
        for (int off = 8; off; off >>= 1) m0 = fmaxf(m0, __shfl_xor_sync(FULL, m0, off));
        float q = __expf(t - m0);
        float C = __ldg(&g_rowmax[b*SS]) + m0;

        float Bc[16], Bn[16];
        #pragma unroll
        for (int i = 0; i < 16; i++) Bc[i] = Bs[0][i][kk];

        for (int c = 0; c < NSUP; c++) {
            if (c > 0) {
                if (lane < 16) qs_sh[c][kk] = q;
                if (lane == 0) Cs_sh[c] = C;
            }
            if (c + 1 < NSUP) {
                #pragma unroll
                for (int i = 0; i < 16; i++) Bn[i] = Bs[c+1][i][kk];
            }
            float s0 = 0.f, s1 = 0.f, s2 = 0.f, s3 = 0.f;
            #pragma unroll
            for (int j = 0; j < 16; j += 4) {
                s0 = fmaf(__shfl_sync(FULL, q, j + 0), Bc[j + 0], s0);
                s1 = fmaf(__shfl_sync(FULL, q, j + 1), Bc[j + 1], s1);
                s2 = fmaf(__shfl_sync(FULL, q, j + 2), Bc[j + 2], s2);
                s3 = fmaf(__shfl_sync(FULL, q, j + 3), Bc[j + 3], s3);
            }
            float v = (s0 + s1) + (s2 + s3);
            C += rc[c];
            if ((c & 7) == 7) {
                float mv = v;
                #pragma unroll
                for (int off = 8; off; off >>= 1)
                    mv = fmaxf(mv, __shfl_xor_sync(FULL, mv, off));
                mv = fmaxf(mv, 1e-37f);
                q = __fdividef(v, mv);
                C += __logf(mv);
            } else {
                q = v;
            }
            #pragma unroll
            for (int i = 0; i < 16; i++) Bc[i] = Bn[i];
        }
    }
    __syncthreads();

    // ---- (c) propagate: warp w handles supers 2w, 2w+1 ----
    #pragma unroll
    for (int ss = 0; ss < 2; ss++) {
        int s = w*2 + ss;
        float q, C;
        if (s == 0) {
            float sv = __ldg(start_logits + kk);
            float sm = sv;
            #pragma unroll
            for (int off = 8; off; off >>= 1) sm = fmaxf(sm, __shfl_xor_sync(FULL, sm, off));
            float se = __expf(sv - sm);
            #pragma unroll
            for (int off = 8; off; off >>= 1) se += __shfl_xor_sync(FULL, se, off);
            float lstart = sv - sm - __logf(se);
            float e0 = __ldg(&g_emp[(size_t)(b*SS)*KK + kk]);
            float t = lstart + e0;
            float m0 = t;
            #pragma unroll
            for (int off = 8; off; off >>= 1) m0 = fmaxf(m0, __shfl_xor_sync(FULL, m0, off));
            q = __expf(t - m0);
            C = __ldg(&g_rowmax[b*SS]) + m0;
        } else {
            q = qs_sh[s][kk];
            C = Cs_sh[s];
        }

        for (int m = 0; m < SUPW; m++) {
            int cl = s*SUPW + m;
            int gc = b*NC + cl;
            if (cl > 0) {
                if (lane < 16) g_qb[gc][kk] = q;
                if (lane == 0) g_Cb[gc] = C;
            }
            if (m + 1 < SUPW) {
                float rl = (lane < 16) ? __ldg(&g_rowlog[gc][lane]) : -3.4e38f;
                float rlmax = rl;
                #pragma unroll
                for (int off = 16; off; off >>= 1)
                    rlmax = fmaxf(rlmax, __shfl_xor_sync(FULL, rlmax, off));
                float smy = __expf(rl - rlmax);

                float col[16];
                #pragma unroll
                for (int i = 0; i < 16; i++)
                    col[i] = __shfl_sync(FULL, smy, i) * __ldg(&g_Rn[gc][i*KK + kk]);

                float s0 = 0.f, s1 = 0.f, s2 = 0.f, s3 = 0.f;
                #pragma unroll
                for (int j = 0; j < 16; j += 4) {
                    s0 = fmaf(__shfl_sync(FULL, q, j + 0), col[j + 0], s0);
                    s1 = fmaf(__shfl_sync(FULL, q, j + 1), col[j + 1], s1);
                    s2 = fmaf(__shfl_sync(FULL, q, j + 2), col[j + 2], s2);
                    s3 = fmaf(__shfl_sync(FULL, q, j + 3), col[j + 3], s3);
                }
                float v = (s0 + s1) + (s2 + s3);
                float mv = v;
                #pragma unroll
                for (int off = 8; off; off >>= 1)
                    mv = fmaxf(mv, __shfl_xor_sync(FULL, mv, off));
                mv = fmaxf(mv, 1e-37f);
                q = __fdividef(v, mv);
                C += __ldg(&g_rmsum[gc]) + rlmax + __logf(mv);
            }
        }
    }
}

// ---------------------------------------------------------------------------
// Phase 3: per-chunk (16 steps) vector recursion from stored boundary.
// ---------------------------------------------------------------------------
__global__ void __launch_bounds__(32) phase3_kernel(
    const float* __restrict__ start_logits, float* __restrict__ out)
{
    int c = blockIdx.x;
    int lane = threadIdx.x;
    int b = c / NC, cl = c % NC;
    int kk = lane & 15;

    float acol[KK];
    #pragma unroll
    for (int j = 0; j < KK; j++) acol[j] = __ldg(&g_A[j*KK + kk]);

    const float* pE = g_E   + (size_t)(b*SS + cl*CH)*KK;
    const float* pP = g_emp + (size_t)(b*SS + cl*CH)*KK;
    const float* prm = g_rowmax + b*SS + cl*CH;
    float* ob = out + (size_t)(b*SS + cl*CH)*KK;

    float bufE[CH], bufP[CH], rm[CH];
    #pragma unroll
    for (int u = 0; u < CH; u++) {
        bufE[u] = __ldg(pE + u*KK + kk);
        bufP[u] = __ldg(pP + u*KK + kk);
        rm[u]   = __ldg(prm + u);
    }

    float q, C;
    if (cl == 0) {
        float sv = __ldg(start_logits + kk);
        float sm = sv;
        #pragma unroll
        for (int off = 8; off; off >>= 1) sm = fmaxf(sm, __shfl_xor_sync(FULL, sm, off));
        float se = __expf(sv - sm);
        #pragma unroll
        for (int off = 8; off; off >>= 1) se += __shfl_xor_sync(FULL, se, off);
        float lstart = sv - sm - __logf(se);

        float a0 = lstart + bufP[0] + rm[0];
        if (lane < 16) ob[kk] = a0;
        q = __expf(fmaxf(lstart + bufP[0], -80.f));
        C = rm[0];
    } else {
        q = __ldg(&g_qb[c][kk]);
        C = __ldg(&g_Cb[c]);
    }

    #pragma unroll
    for (int u = 0; u < CH; u++) {
        if (cl == 0 && u == 0) continue;
        float s0 = 0.f, s1 = 0.f, s2 = 0.f, s3 = 0.f;
        #pragma unroll
        for (int j = 0; j < KK; j += 4) {
            s0 = fmaf(__shfl_sync(FULL, q, j + 0), acol[j + 0], s0);
            s1 = fmaf(__shfl_sync(FULL, q, j + 1), acol[j + 1], s1);
            s2 = fmaf(__shfl_sync(FULL, q, j + 2), acol[j + 2], s2);
            s3 = fmaf(__shfl_sync(FULL, q, j + 3), acol[j + 3], s3);
        }
        float ssum = (s0 + s1) + (s2 + s3);
        ssum = fmaxf(ssum, 1e-37f);
        float ov = C + rm[u] + bufP[u] + __logf(ssum);
        if (lane < 16) ob[u*KK + kk] = ov;
        q = ssum * bufE[u];
        C += rm[u];
    }
}

// ---------------------------------------------------------------------------
extern "C" void kernel_launch(void* const* d_in, const int* in_sizes, int n_in,
                              void* d_out, int out_size) {
    const float* y   = (const float*)d_in[0];
    const float* z   = (const float*)d_in[1];
    const float* st  = (const float*)d_in[2];
    const float* tr  = (const float*)d_in[3];
    const float* mu  = (const float*)d_in[4];
    const float* lv  = (const float*)d_in[5];
    const float* wz  = (const float*)d_in[6];
    const float* ws  = (const float*)d_in[7];
    const float* bd  = (const float*)d_in[8];
    float* out = (float*)d_out;

    setup_kernel<<<KK, 32>>>(lv, ws, tr);
    emissions_kernel<<<NS/SPB, TPB>>>(y, z, wz, ws, bd, mu);
    phase1_kernel<<<TOTCH, 32>>>();
    phase1b_kernel<<<TOTSUP, 32>>>();
    phase2_kernel<<<BB, 256>>>(st);
    phase3_kernel<<<TOTCH, 32>>>(st, out);
}

// round 8
// speedup vs baseline: 1.0690x; 1.0208x over previous
#include <cuda_runtime.h>

#define BB 16
#define SS 2048
#define KK 16
#define LL 64
#define II 256
#define NS (BB*SS)        // 32768
#define CH 16
#define NC (SS/CH)        // 128 chunks per batch
#define TOTCH (BB*NC)     // 2048 chunks total
#define SUPW 8            // chunks per super-chunk
#define NSUP (NC/SUPW)    // 16 super-chunks per batch

#define SPB 16            // samples per emissions block
#define TPB 256

#define FULL 0xffffffffu

// ---- packed f32x2 helpers (sm_100a Blackwell) ----
typedef unsigned long long u64t;
#define FMA2(d,a,b,c) asm volatile("fma.rn.f32x2 %0, %1, %2, %3;" : "=l"(d) : "l"(a), "l"(b), "l"(c))
#define ADD2(d,a,b)   asm volatile("add.rn.f32x2 %0, %1, %2;" : "=l"(d) : "l"(a), "l"(b))
#define MUL2(d,a,b)   asm volatile("mul.rn.f32x2 %0, %1, %2;" : "=l"(d) : "l"(a), "l"(b))
#define PK2(d,lo,hi)  asm volatile("mov.b64 %0, {%1, %2};" : "=l"(d) : "r"(lo), "r"(hi))
#define UPK2(lo,hi,s) asm volatile("mov.b64 {%0, %1}, %2;" : "=r"(lo), "=r"(hi) : "l"(s))
#define LDS2(a,b,addr) asm volatile("ld.shared.v2.u64 {%0, %1}, [%2];" : "=l"(a), "=l"(b) : "r"(addr))

__device__ __forceinline__ unsigned s2u(const void* p) {
    unsigned r;
    asm("{ .reg .u64 t; cvta.to.shared.u64 t, %1; cvt.u32.u64 %0, t; }" : "=r"(r) : "l"(p));
    return r;
}

// Scratch (device globals; no allocation allowed)
__device__ __align__(16) float g_E[NS*KK];            // exp(clamp(em - rowmax, -80))
__device__ __align__(16) float g_emp[NS*KK];          // em - rowmax
__device__ __align__(16) float g_rowmax[NS];
__device__ __align__(16) float g_invvar[KK*LL];
__device__ __align__(16) float g_nm[KK*LL];           // -mu
__device__ float g_lvsum[KK];
__device__ float g_ws2[KK];
__device__ float g_A[KK*KK];
__device__ __align__(16) float g_Rn[TOTCH][KK*KK];    // per-chunk matrix, row max = 1
__device__ __align__(16) float g_rowlog[TOTCH][KK];   // per-row log scale
__device__ __align__(16) float g_rmsum[TOTCH];
__device__ float g_qb[TOTCH][KK];
__device__ float g_Cb[TOTCH];

// ---------------------------------------------------------------------------
// Setup: one warp-block per state k.
// ---------------------------------------------------------------------------
__global__ void __launch_bounds__(32) setup_kernel(
    const float* __restrict__ prior_logvar,
    const float* __restrict__ Ws,
    const float* __restrict__ trans,
    const float* __restrict__ mu)
{
    int w = blockIdx.x;
    int lane = threadIdx.x;

    float s = 0.f;
    #pragma unroll
    for (int e = 0; e < 2; e++) {
        int idx = w*LL + lane + 32*e;
        float lv = __ldg(prior_logvar + idx);
        g_invvar[idx] = 1.0f / (expf(lv) + 1e-8f);
        g_nm[idx] = -__ldg(mu + idx);
        s += lv;
    }
    #pragma unroll
    for (int off = 16; off; off >>= 1) s += __shfl_xor_sync(FULL, s, off);
    if (lane == 0) g_lvsum[w] = s;

    float s2 = 0.f;
    #pragma unroll
    for (int e = 0; e < 8; e++) {
        float v = __ldg(Ws + w*II + lane + 32*e);
        s2 = fmaf(v, v, s2);
    }
    #pragma unroll
    for (int off = 16; off; off >>= 1) s2 += __shfl_xor_sync(FULL, s2, off);
    if (lane == 0) g_ws2[w] = s2;

    float v = (lane < 16) ? __ldg(trans + w*KK + (lane & 15)) : -1e30f;
    float mx = v;
    #pragma unroll
    for (int off = 8; off; off >>= 1) mx = fmaxf(mx, __shfl_xor_sync(FULL, mx, off));
    float ex = (lane < 16) ? expf(v - mx) : 0.f;
    float se = ex;
    #pragma unroll
    for (int off = 8; off; off >>= 1) se += __shfl_xor_sync(FULL, se, off);
    if (lane < 16) g_A[w*KK + lane] = expf(v - mx - logf(se));
}

// ---------------------------------------------------------------------------
// Emissions (packed f32x2 math)
// ---------------------------------------------------------------------------
__global__ void __launch_bounds__(TPB) emissions_kernel(
    const float* __restrict__ Y, const float* __restrict__ Z,
    const float* __restrict__ Wz, const float* __restrict__ Ws,
    const float* __restrict__ bdec)
{
    __shared__ __align__(16) float z_a[LL][SPB];      // [l][s]
    __shared__ __align__(16) float z_b[SPB][LL+4];    // [s][l] padded (272B rows)
    __shared__ __align__(16) float d_sh[SPB][II];
    __shared__ __align__(16) float ws_sh[KK][II+4];   // 1040B rows

    int tid = threadIdx.x;
    int s0 = blockIdx.x * SPB;

    #pragma unroll
    for (int e = 0; e < (SPB*LL)/TPB; e++) {
        int idx = tid + TPB*e;
        int s = idx >> 6, l = idx & 63;
        float v = Z[(s0 + s)*LL + l];
        z_a[l][s] = v;
        z_b[s][l] = v;
    }
    #pragma unroll
    for (int e = 0; e < (KK*II)/TPB; e++) {
        int idx = tid + TPB*e;
        ws_sh[idx >> 8][idx & 255] = Ws[idx];
    }
    __syncthreads();

    // ---- Phase A: base = b_dec + z @ Wz (packed pairs over samples) ----
    {
        u64t bp[8];
        float bd = __ldg(bdec + tid);
        u64t bdp; PK2(bdp, __float_as_uint(bd), __float_as_uint(bd));
        #pragma unroll
        for (int p = 0; p < 8; p++) bp[p] = bdp;

        unsigned za0 = s2u(&z_a[0][0]);
        #pragma unroll 4
        for (int l = 0; l < LL; l++) {
            float wz = __ldg(Wz + l*II + tid);
            u64t wzp; PK2(wzp, __float_as_uint(wz), __float_as_uint(wz));
            unsigned row = za0 + l*(SPB*4);
            u64t z0,z1,z2,z3,z4,z5,z6,z7;
            LDS2(z0, z1, row);
            LDS2(z2, z3, row + 16);
            LDS2(z4, z5, row + 32);
            LDS2(z6, z7, row + 48);
            FMA2(bp[0], z0, wzp, bp[0]);
            FMA2(bp[1], z1, wzp, bp[1]);
            FMA2(bp[2], z2, wzp, bp[2]);
            FMA2(bp[3], z3, wzp, bp[3]);
            FMA2(bp[4], z4, wzp, bp[4]);
            FMA2(bp[5], z5, wzp, bp[5]);
            FMA2(bp[6], z6, wzp, bp[6]);
            FMA2(bp[7], z7, wzp, bp[7]);
        }
        #pragma unroll
        for (int p = 0; p < 8; p++) {
            unsigned u0, u1; UPK2(u0, u1, bp[p]);
            int s = 2*p;
            float y0 = __ldg(Y + (s0 + s)*II + tid);
            float y1 = __ldg(Y + (s0 + s + 1)*II + tid);
            d_sh[s][tid]     = y0 - __uint_as_float(u0);
            d_sh[s + 1][tid] = y1 - __uint_as_float(u1);
        }
    }
    __syncthreads();

    // ---- Phase B: thread (sample, state) ----
    int si = tid >> 4;
    int k  = tid & 15;

    // cooperative ||d||^2
    float sd = 0.f;
    #pragma unroll
    for (int t = 0; t < 16; t++) {
        float dv = d_sh[si][t*16 + k];
        sd = fmaf(dv, dv, sd);
    }
    #pragma unroll
    for (int off = 8; off; off >>= 1) sd += __shfl_xor_sync(FULL, sd, off);

    // dot(d, Ws_k) packed
    float dot;
    {
        unsigned drow = s2u(&d_sh[si][0]);
        unsigned wrow = s2u(&ws_sh[k][0]);
        u64t a0 = 0ull, a1 = 0ull;
        #pragma unroll 8
        for (int i = 0; i < II/4; i++) {
            u64t d0, d1, w0, w1;
            LDS2(d0, d1, drow + i*16);
            LDS2(w0, w1, wrow + i*16);
            FMA2(a0, d0, w0, a0);
            FMA2(a1, d1, w1, a1);
        }
        unsigned l0, h0, l1, h1;
        UPK2(l0, h0, a0); UPK2(l1, h1, a1);
        dot = (__uint_as_float(l0) + __uint_as_float(h0))
            + (__uint_as_float(l1) + __uint_as_float(h1));
    }
    float accy = sd - 2.f*dot + __ldg(&g_ws2[k]);

    // z-prior quadratic packed: sum (z-mu)^2 * invvar
    float accz;
    {
        unsigned zrow = s2u(&z_b[si][0]);
        const ulonglong2* nm2 = (const ulonglong2*)(g_nm + k*LL);
        const ulonglong2* iv2 = (const ulonglong2*)(g_invvar + k*LL);
        u64t a0 = 0ull, a1 = 0ull;
        #pragma unroll
        for (int i = 0; i < LL/4; i++) {
            u64t z0, z1;
            LDS2(z0, z1, zrow + i*16);
            ulonglong2 mv = __ldg(nm2 + i);
            ulonglong2 vv = __ldg(iv2 + i);
            u64t t0, t1;
            ADD2(t0, z0, mv.x);
            ADD2(t1, z1, mv.y);
            MUL2(t0, t0, t0);
            MUL2(t1, t1, t1);
            FMA2(a0, t0, vv.x, a0);
            FMA2(a1, t1, vv.y, a1);
        }
        unsigned l0, h0, l1, h1;
        UPK2(l0, h0, a0); UPK2(l1, h1, a1);
        accz = (__uint_as_float(l0) + __uint_as_float(h0))
             + (__uint_as_float(l1) + __uint_as_float(h1));
    }

    const float LLOG2PI = 117.62413f;  // 64 * log(2*pi)
    float em = -0.5f*accy - 0.5f*(__ldg(&g_lvsum[k]) + accz + LLOG2PI);

    float m = em;
    #pragma unroll
    for (int off = 8; off; off >>= 1)
        m = fmaxf(m, __shfl_xor_sync(FULL, m, off));

    float emp = em - m;
    float E = __expf(fmaxf(emp, -80.f));

    int sample = s0 + si;
    g_E[sample*KK + k]   = E;
    g_emp[sample*KK + k] = emp;
    if (k == 0) g_rowmax[sample] = m;
}

// ---------------------------------------------------------------------------
// Phase 1: per-chunk (16 steps) matrix product R_c = prod M_t, M_t = A diag(E_t).
// ---------------------------------------------------------------------------
__global__ void __launch_bounds__(32) phase1_kernel() {
    int c = blockIdx.x;
    int lane = threadIdx.x;
    int b = c / NC, cl = c % NC;
    int i = lane >> 1, h = lane & 1;

    float a[KK][8];
    #pragma unroll
    for (int j = 0; j < KK; j++)
        #pragma unroll
        for (int kk = 0; kk < 8; kk++)
            a[j][kk] = g_A[j*KK + h*8 + kk];

    float R[8];
    #pragma unroll
    for (int kk = 0; kk < 8; kk++)
        R[kk] = (i == h*8 + kk) ? 1.f : 0.f;

    float rowlog = 0.f, rmsum = 0.f;

    int t0 = b*SS + cl*CH;
    int us = (cl == 0) ? 1 : 0;
    const float* prm = g_rowmax + t0;

    float E[8], En[8];
    {
        const float4* p4 = (const float4*)(g_E + (size_t)(t0 + us)*KK + h*8);
        float4 q0 = __ldg(p4+0), q1 = __ldg(p4+1);
        E[0]=q0.x; E[1]=q0.y; E[2]=q0.z; E[3]=q0.w;
        E[4]=q1.x; E[5]=q1.y; E[6]=q1.z; E[7]=q1.w;
    }
    float rmc = __ldg(prm + us), rmn = 0.f;

    #pragma unroll
    for (int u = 0; u < CH; u++) {
        if (u < us) continue;
        if (u + 1 < CH) {
            const float4* p4 = (const float4*)(g_E + (size_t)(t0 + u + 1)*KK + h*8);
            float4 q0 = __ldg(p4+0), q1 = __ldg(p4+1);
            En[0]=q0.x; En[1]=q0.y; En[2]=q0.z; En[3]=q0.w;
            En[4]=q1.x; En[5]=q1.y; En[6]=q1.z; En[7]=q1.w;
            rmn = __ldg(prm + u + 1);
        }
        rmsum += rmc;

        float rp[8];
        #pragma unroll
        for (int j = 0; j < 8; j++) rp[j] = __shfl_xor_sync(FULL, R[j], 1);
        float rlo[8], rhi[8];
        #pragma unroll
        for (int j = 0; j < 8; j++) {
            rlo[j] = h ? rp[j] : R[j];
            rhi[j] = h ? R[j] : rp[j];
        }
        float nw[8];
        #pragma unroll
        for (int kk = 0; kk < 8; kk++) {
            float s0 = 0.f, s1 = 0.f;
            #pragma unroll
            for (int j = 0; j < 8; j++) {
                s0 = fmaf(rlo[j], a[j][kk],   s0);
                s1 = fmaf(rhi[j], a[j+8][kk], s1);
            }
            nw[kk] = (s0 + s1) * E[kk];
        }
        #pragma unroll
        for (int kk = 0; kk < 8; kk++) R[kk] = nw[kk];

        if (((u + 1) & 7) == 0) {
            float mx = R[0];
            #pragma unroll
            for (int kk = 1; kk < 8; kk++) mx = fmaxf(mx, R[kk]);
            mx = fmaxf(mx, __shfl_xor_sync(FULL, mx, 1));
            mx = fmaxf(mx, 1e-37f);
            float inv = __fdividef(1.f, mx);
            #pragma unroll
            for (int kk = 0; kk < 8; kk++) R[kk] *= inv;
            rowlog += __logf(mx);
        }

        #pragma unroll
        for (int kk = 0; kk < 8; kk++) E[kk] = En[kk];
        rmc = rmn;
    }

    #pragma unroll
    for (int kk = 0; kk < 8; kk++)
        g_Rn[c][i*KK + h*8 + kk] = R[kk];
    if (h == 0) g_rowlog[c][i] = rowlog;
    if (lane == 0) g_rmsum[c] = rmsum;
}

// ---------------------------------------------------------------------------
// Phase 2 (fused with super-combine): one 256-thread block per batch.
// (0) stage all 128 chunk matrices + logs into smem;
// (1) 8 warps build 16 pre-scaled super matrices (8-chunk products);
// (2) warp 0 runs 16 serial combines -> super boundaries;
// (3) 8 warps propagate boundaries down to all 128 chunk starts.
// ---------------------------------------------------------------------------
__global__ void __launch_bounds__(256) phase2_kernel(const float* __restrict__ start_logits) {
    extern __shared__ __align__(16) float sm2[];
    float* Rs   = sm2;                 // [NC][256]
    float* rls  = Rs + NC*256;         // [NC][16]
    float* rms  = rls + NC*16;         // [NC]
    float* Ss   = rms + NC;            // [NSUP][256] pre-scaled
    float* srcv = Ss + NSUP*256;       // [NSUP]
    float* qs   = srcv + NSUP;         // [NSUP][16]
    float* Cs   = qs + NSUP*16;        // [NSUP]

    int b = blockIdx.x;
    int tid = threadIdx.x;
    int w = tid >> 5, lane = tid & 31;
    int kk = lane & 15;

    // ---- (0) stage-in ----
    {
        const float4* src = (const float4*)(&g_Rn[b*NC][0]);
        float4* dst = (float4*)Rs;
        for (int i = tid; i < NC*64; i += 256) dst[i] = __ldg(src + i);
        const float4* s2 = (const float4*)(&g_rowlog[b*NC][0]);
        float4* d2 = (float4*)rls;
        for (int i = tid; i < NC*4; i += 256) d2[i] = __ldg(s2 + i);
        if (tid < NC) rms[tid] = __ldg(&g_rmsum[b*NC + tid]);
    }
    __syncthreads();

    int iRow = lane >> 1, h = lane & 1;

    // ---- (1) super-combine: warp w -> supers w and w+8 ----
    #pragma unroll
    for (int ss2 = 0; ss2 < 2; ss2++) {
        int s = w + ss2*8;
        int c0 = s*SUPW;

        float acc[8];
        {
            const float4* p = (const float4*)(Rs + c0*256 + iRow*16 + h*8);
            float4 r0 = p[0], r1 = p[1];
            acc[0]=r0.x; acc[1]=r0.y; acc[2]=r0.z; acc[3]=r0.w;
            acc[4]=r1.x; acc[5]=r1.y; acc[6]=r1.z; acc[7]=r1.w;
        }
        float rlA = rls[c0*16 + iRow];

        for (int m = 1; m < SUPW; m++) {
            int cm = c0 + m;
            float rl = (lane < 16) ? rls[cm*16 + lane] : -3.4e38f;
            float rlmax = rl;
            #pragma unroll
            for (int off = 16; off; off >>= 1)
                rlmax = fmaxf(rlmax, __shfl_xor_sync(FULL, rlmax, off));
            float sB = __expf(rl - rlmax);

            // gather full row of acc
            float rp[8];
            #pragma unroll
            for (int j = 0; j < 8; j++) rp[j] = __shfl_xor_sync(FULL, acc[j], 1);
            float ar[16];
            #pragma unroll
            for (int j = 0; j < 8; j++) {
                ar[j]   = h ? rp[j]  : acc[j];
                ar[j+8] = h ? acc[j] : rp[j];
            }

            float nw[8];
            #pragma unroll
            for (int kk2 = 0; kk2 < 8; kk2++) nw[kk2] = 0.f;
            #pragma unroll
            for (int j = 0; j < 16; j++) {
                const float4* pb = (const float4*)(Rs + cm*256 + j*16 + h*8);
                float4 b0 = pb[0], b1 = pb[1];
                float aj = ar[j] * __shfl_sync(FULL, sB, j);
                nw[0] = fmaf(aj, b0.x, nw[0]);
                nw[1] = fmaf(aj, b0.y, nw[1]);
                nw[2] = fmaf(aj, b0.z, nw[2]);
                nw[3] = fmaf(aj, b0.w, nw[3]);
                nw[4] = fmaf(aj, b1.x, nw[4]);
                nw[5] = fmaf(aj, b1.y, nw[5]);
                nw[6] = fmaf(aj, b1.z, nw[6]);
                nw[7] = fmaf(aj, b1.w, nw[7]);
            }
            float mx = nw[0];
            #pragma unroll
            for (int kk2 = 1; kk2 < 8; kk2++) mx = fmaxf(mx, nw[kk2]);
            mx = fmaxf(mx, __shfl_xor_sync(FULL, mx, 1));
            mx = fmaxf(mx, 1e-37f);
            float inv = __fdividef(1.f, mx);
            #pragma unroll
            for (int kk2 = 0; kk2 < 8; kk2++) acc[kk2] = nw[kk2] * inv;
            rlA += rlmax + __logf(mx);
        }

        // pre-scale rows and write super matrix
        float srlmax = rlA;
        #pragma unroll
        for (int off = 16; off; off >>= 1)
            srlmax = fmaxf(srlmax, __shfl_xor_sync(FULL, srlmax, off));
        float rsc = __expf(rlA - srlmax);
        #pragma unroll
        for (int kk2 = 0; kk2 < 8; kk2++)
            Ss[s*256 + iRow*16 + h*8 + kk2] = acc[kk2] * rsc;
        if (lane == 0) {
            float t = 0.f;
            #pragma unroll
            for (int m = 0; m < SUPW; m++) t += rms[c0 + m];
            srcv[s] = t + srlmax;
        }
    }
    __syncthreads();

    // ---- (2) warp 0: serial combines over 16 supers ----
    if (w == 0) {
        float sv = __ldg(start_logits + kk);
        float sm = sv;
        #pragma unroll
        for (int off = 8; off; off >>= 1) sm = fmaxf(sm, __shfl_xor_sync(FULL, sm, off));
        float se = __expf(sv - sm);
        #pragma unroll
        for (int off = 8; off; off >>= 1) se += __shfl_xor_sync(FULL, se, off);
        float lstart = sv - sm - __logf(se);

        float e0 = __ldg(&g_emp[(size_t)(b*SS)*KK + kk]);
        float t = lstart + e0;
        float m0 = t;
        #pragma unroll
        for (int off = 8; off; off >>= 1) m0 = fmaxf(m0, __shfl_xor_sync(FULL, m0, off));
        float q = __expf(t - m0);
        float C = __ldg(&g_rowmax[b*SS]) + m0;

        float Bc[16], Bn[16];
        #pragma unroll
        for (int i = 0; i < 16; i++) Bc[i] = Ss[i*16 + kk];

        for (int c = 0; c < NSUP; c++) {
            if (c > 0) {
                if (lane < 16) qs[c*16 + kk] = q;
                if (lane == 0) Cs[c] = C;
            }
            if (c + 1 < NSUP) {
                #pragma unroll
                for (int i = 0; i < 16; i++) Bn[i] = Ss[(c+1)*256 + i*16 + kk];
            }
            float s0 = 0.f, s1 = 0.f, s2 = 0.f, s3 = 0.f;
            #pragma unroll
            for (int j = 0; j < 16; j += 4) {
                s0 = fmaf(__shfl_sync(FULL, q, j + 0), Bc[j + 0], s0);
                s1 = fmaf(__shfl_sync(FULL, q, j + 1), Bc[j + 1], s1);
                s2 = fmaf(__shfl_sync(FULL, q, j + 2), Bc[j + 2], s2);
                s3 = fmaf(__shfl_sync(FULL, q, j + 3), Bc[j + 3], s3);
            }
            float v = (s0 + s1) + (s2 + s3);
            C += srcv[c];
            if ((c & 7) == 7) {
                float mv = v;
                #pragma unroll
                for (int off = 8; off; off >>= 1)
                    mv = fmaxf(mv, __shfl_xor_sync(FULL, mv, off));
                mv = fmaxf(mv, 1e-37f);
                q = __fdividef(v, mv);
                C += __logf(mv);
            } else {
                q = v;
            }
            #pragma unroll
            for (int i = 0; i < 16; i++) Bc[i] = Bn[i];
        }
    }
    __syncthreads();

    // ---- (3) propagate: warp w -> supers w, w+8 ----
    #pragma unroll
    for (int ss2 = 0; ss2 < 2; ss2++) {
        int s = w + ss2*8;
        float q, C;
        if (s == 0) {
            float sv = __ldg(start_logits + kk);
            float sm = sv;
            #pragma unroll
            for (int off = 8; off; off >>= 1) sm = fmaxf(sm, __shfl_xor_sync(FULL, sm, off));
            float se = __expf(sv - sm);
            #pragma unroll
            for (int off = 8; off; off >>= 1) se += __shfl_xor_sync(FULL, se, off);
            float lstart = sv - sm - __logf(se);
            float e0 = __ldg(&g_emp[(size_t)(b*SS)*KK + kk]);
            float t = lstart + e0;
            float m0 = t;
            #pragma unroll
            for (int off = 8; off; off >>= 1) m0 = fmaxf(m0, __shfl_xor_sync(FULL, m0, off));
            q = __expf(t - m0);
            C = __ldg(&g_rowmax[b*SS]) + m0;
        } else {
            q = qs[s*16 + kk];
            C = Cs[s];
        }

        for (int m = 0; m < SUPW; m++) {
            int cl = s*SUPW + m;
            int gc = b*NC + cl;
            if (cl > 0) {
                if (lane < 16) g_qb[gc][kk] = q;
                if (lane == 0) g_Cb[gc] = C;
            }
            if (m + 1 < SUPW) {
                float rl = (lane < 16) ? rls[cl*16 + lane] : -3.4e38f;
                float rlmax = rl;
                #pragma unroll
                for (int off = 16; off; off >>= 1)
                    rlmax = fmaxf(rlmax, __shfl_xor_sync(FULL, rlmax, off));
                float smy = __expf(rl - rlmax);
                float qsc = q * smy;   // lanes >= 16 contribute 0 (unused)

                float s0 = 0.f, s1 = 0.f, s2 = 0.f, s3 = 0.f;
                #pragma unroll
                for (int j = 0; j < 16; j += 4) {
                    s0 = fmaf(__shfl_sync(FULL, qsc, j + 0), Rs[cl*256 + (j+0)*16 + kk], s0);
                    s1 = fmaf(__shfl_sync(FULL, qsc, j + 1), Rs[cl*256 + (j+1)*16 + kk], s1);
                    s2 = fmaf(__shfl_sync(FULL, qsc, j + 2), Rs[cl*256 + (j+2)*16 + kk], s2);
                    s3 = fmaf(__shfl_sync(FULL, qsc, j + 3), Rs[cl*256 + (j+3)*16 + kk], s3);
                }
                float v = (s0 + s1) + (s2 + s3);
                float mv = v;
                #pragma unroll
                for (int off = 8; off; off >>= 1)
                    mv = fmaxf(mv, __shfl_xor_sync(FULL, mv, off));
                mv = fmaxf(mv, 1e-37f);
                q = __fdividef(v, mv);
                C += rms[cl] + rlmax + __logf(mv);
            }
        }
    }
}

// ---------------------------------------------------------------------------
// Phase 3: per-chunk (16 steps) vector recursion from stored boundary.
// ---------------------------------------------------------------------------
__global__ void __launch_bounds__(32) phase3_kernel(
    const float* __restrict__ start_logits, float* __restrict__ out)
{
    int c = blockIdx.x;
    int lane = threadIdx.x;
    int b = c / NC, cl = c % NC;
    int kk = lane & 15;

    float acol[KK];
    #pragma unroll
    for (int j = 0; j < KK; j++) acol[j] = __ldg(&g_A[j*KK + kk]);

    const float* pE = g_E   + (size_t)(b*SS + cl*CH)*KK;
    const float* pP = g_emp + (size_t)(b*SS + cl*CH)*KK;
    const float* prm = g_rowmax + b*SS + cl*CH;
    float* ob = out + (size_t)(b*SS + cl*CH)*KK;

    float bufE[CH], bufP[CH], rm[CH];
    #pragma unroll
    for (int u = 0; u < CH; u++) {
        bufE[u] = __ldg(pE + u*KK + kk);
        bufP[u] = __ldg(pP + u*KK + kk);
        rm[u]   = __ldg(prm + u);
    }

    float q, C;
    if (cl == 0) {
        float sv = __ldg(start_logits + kk);
        float sm = sv;
        #pragma unroll
        for (int off = 8; off; off >>= 1) sm = fmaxf(sm, __shfl_xor_sync(FULL, sm, off));
        float se = __expf(sv - sm);
        #pragma unroll
        for (int off = 8; off; off >>= 1) se += __shfl_xor_sync(FULL, se, off);
        float lstart = sv - sm - __logf(se);

        float a0 = lstart + bufP[0] + rm[0];
        if (lane < 16) ob[kk] = a0;
        q = __expf(fmaxf(lstart + bufP[0], -80.f));
        C = rm[0];
    } else {
        q = __ldg(&g_qb[c][kk]);
        C = __ldg(&g_Cb[c]);
    }

    #pragma unroll
    for (int u = 0; u < CH; u++) {
        if (cl == 0 && u == 0) continue;
        float s0 = 0.f, s1 = 0.f, s2 = 0.f, s3 = 0.f;
        #pragma unroll
        for (int j = 0; j < KK; j += 4) {
            s0 = fmaf(__shfl_sync(FULL, q, j + 0), acol[j + 0], s0);
            s1 = fmaf(__shfl_sync(FULL, q, j + 1), acol[j + 1], s1);
            s2 = fmaf(__shfl_sync(FULL, q, j + 2), acol[j + 2], s2);
            s3 = fmaf(__shfl_sync(FULL, q, j + 3), acol[j + 3], s3);
        }
        float ssum = (s0 + s1) + (s2 + s3);
        ssum = fmaxf(ssum, 1e-37f);
        float ov = C + rm[u] + bufP[u] + __logf(ssum);
        if (lane < 16) ob[u*KK + kk] = ov;
        q = ssum * bufE[u];
        C += rm[u];
    }
}

// ---------------------------------------------------------------------------
extern "C" void kernel_launch(void* const* d_in, const int* in_sizes, int n_in,
                              void* d_out, int out_size) {
    const float* y   = (const float*)d_in[0];
    const float* z   = (const float*)d_in[1];
    const float* st  = (const float*)d_in[2];
    const float* tr  = (const float*)d_in[3];
    const float* mu  = (const float*)d_in[4];
    const float* lv  = (const float*)d_in[5];
    const float* wz  = (const float*)d_in[6];
    const float* ws  = (const float*)d_in[7];
    const float* bd  = (const float*)d_in[8];
    float* out = (float*)d_out;

    int p2_smem = (NC*256 + NC*16 + NC + NSUP*256 + NSUP + NSUP*16 + NSUP) * sizeof(float);
    cudaFuncSetAttribute(phase2_kernel,
                         cudaFuncAttributeMaxDynamicSharedMemorySize, p2_smem);

    setup_kernel<<<KK, 32>>>(lv, ws, tr, mu);
    emissions_kernel<<<NS/SPB, TPB>>>(y, z, wz, ws, bd);
    phase1_kernel<<<TOTCH, 32>>>();
    phase2_kernel<<<BB, 256, p2_smem>>>(st);
    phase3_kernel<<<TOTCH, 32>>>(st, out);
}